// round 11
// baseline (speedup 1.0000x reference)
#include <cuda_runtime.h>

// LocalActivationUnit: score[b,t] = relu([q,k,q-k,q*k] @ W0 + b0) @ W1 + b1
// Folded:  h = qA_b + k . C_b ; score = relu(h) @ W1 + b1.
//
// R10: 256 threads/CTA, 4x8 per-thread microtile, 16 warps/SM (2 CTAs).
//      A loaded as float4 per 4 p-steps (S=132, 16B-aligned rows).
//      e-permuted key layout matches permuted sC rows; conflict-free STS/LDS.

#define NB 1024
#define NT 200
#define NE 128
#define NH 64
#define CHUNK 128
#define S 132   // sA row stride (floats): %4==0 for LDS.128, 4-bank row skew

__device__ __forceinline__ unsigned long long pack2(float x) {
    unsigned long long r;
    asm("mov.b64 %0, {%1, %1};" : "=l"(r) : "r"(__float_as_uint(x)));
    return r;
}
__device__ __forceinline__ void ffma2(unsigned long long &acc, unsigned long long a,
                                      unsigned long long b) {
    asm("fma.rn.f32x2 %0, %1, %2, %0;" : "+l"(acc) : "l"(a), "l"(b));
}
__device__ __forceinline__ float2 unpack2(unsigned long long v) {
    unsigned int lo, hi;
    asm("mov.b64 {%0, %1}, %2;" : "=r"(lo), "=r"(hi) : "l"(v));
    return make_float2(__uint_as_float(lo), __uint_as_float(hi));
}

__global__ void __launch_bounds__(256, 2)
lau_kernel(const float* __restrict__ query,
           const float* __restrict__ keys,
           const float* __restrict__ W0,
           const float* __restrict__ b0,
           const float* __restrict__ W1,
           const float* __restrict__ b1,
           float* __restrict__ out)
{
    extern __shared__ float smem[];
    float* sC  = smem;                 // [128][64] rows in permuted-p order
    float* sA  = smem + NE * NH;       // [CHUNK][S] keys, e-permuted within row
    float* sq  = sA + CHUNK * S;       // [128]
    float* sqA = sq + NE;              // [64]

    const int tid = threadIdx.x;
    const int b   = blockIdx.x;

    // ---- load q ----
    if (tid < NE) sq[tid] = query[b * NE + tid];
    __syncthreads();

    // ---- precompute C_b into smem (rows permuted: p -> e(p)=4*(p&31)+(p>>5)) ----
    const float* W0a = W0;
    const float* W0b = W0 + 128 * NH;
    const float* W0c = W0 + 256 * NH;
    const float* W0d = W0 + 384 * NH;
    #pragma unroll
    for (int j = 0; j < 8; j++) {
        int f = tid + 256 * j;          // float4 index, [0, 2048)
        int p = f >> 4;                 // 16 float4 per row
        int c = f & 15;
        int e = 4 * (p & 31) + (p >> 5);
        float qe = sq[e];
        float4 wb = *(const float4*)(W0b + e * NH + c * 4);
        float4 wc = *(const float4*)(W0c + e * NH + c * 4);
        float4 wd = *(const float4*)(W0d + e * NH + c * 4);
        float4 cv;
        cv.x = (wb.x - wc.x) + qe * wd.x;
        cv.y = (wb.y - wc.y) + qe * wd.y;
        cv.z = (wb.z - wc.z) + qe * wd.z;
        cv.w = (wb.w - wc.w) + qe * wd.w;
        *(float4*)&sC[f * 4] = cv;
    }
    // qA partials: 4 groups of 32 e-terms, scratch in sA
    {
        int h = tid & 63, g = tid >> 6;
        float ps = 0.f;
        int e0 = g * 32;
        #pragma unroll 4
        for (int e = e0; e < e0 + 32; e++)
            ps += sq[e] * (W0a[e * NH + h] + W0c[e * NH + h]);
        sA[g * 64 + h] = ps;
    }
    __syncthreads();
    if (tid < NH)
        sqA[tid] = b0[tid] + sA[tid] + sA[64 + tid] + sA[128 + tid] + sA[192 + tid];
    // (loop-start __syncthreads orders this vs. sA reuse; second sync in loop
    //  orders sqA visibility vs. GEMM reads)

    // ---- per-thread constants ----
    const int ty = tid >> 3;            // 0..31 -> 4 rows each
    const int tx = tid & 7;             // 0..7  -> cols {tx*4..+3, 32+tx*4..+3}
    float w1v[8];
    *(float4*)&w1v[0] = *(const float4*)(W1 + tx * 4);
    *(float4*)&w1v[4] = *(const float4*)(W1 + 32 + tx * 4);
    const float b1v = b1[0];
    const float* bp = sC + tx * 4;
    const unsigned gmask = 0xffu << ((tid & 31) & 24);  // 8-lane shfl group

    // ---- main loop over T in 128-row chunks ----
    for (int t0 = 0; t0 < NT; t0 += CHUNK) {
        const int rows = min(CHUNK, NT - t0);
        __syncthreads();   // previous GEMM done reading sA

        // loader: lane c4 of each row scatters its 4 floats to words
        // {c4, 32+c4, 64+c4, 96+c4}  (bank = 4*row + c4 + off mod 32: conflict-free)
        for (int f = tid; f < rows * 32; f += 256) {
            int row = f >> 5, c4 = f & 31;
            float4 v = *(const float4*)(keys + ((long)b * NT + t0 + row) * NE + c4 * 4);
            float* base = sA + row * S + c4;
            base[0]  = v.x;
            base[32] = v.y;
            base[64] = v.z;
            base[96] = v.w;
        }
        __syncthreads();

        if (ty * 4 < rows) {
            // GEMM: acc[4 rows][4 col-pairs], K=128 (permuted order, matches sC)
            unsigned long long acc[4][4];
            #pragma unroll
            for (int r = 0; r < 4; r++)
                #pragma unroll
                for (int c = 0; c < 4; c++) acc[r][c] = 0ull;

            const float* ap = sA + (ty * 4) * S;
            #pragma unroll 2
            for (int pb = 0; pb < NE / 4; pb++) {
                float av[4][4];
                #pragma unroll
                for (int r = 0; r < 4; r++)
                    *(float4*)av[r] = *(const float4*)(ap + r * S + pb * 4);
                #pragma unroll
                for (int j = 0; j < 4; j++) {
                    const float* be = bp + (pb * 4 + j) * NH;
                    ulonglong2 blo = *(const ulonglong2*)be;        // cols tx*4..+3
                    ulonglong2 bhi = *(const ulonglong2*)(be + 32); // cols 32+tx*4..+3
                    #pragma unroll
                    for (int r = 0; r < 4; r++) {
                        unsigned long long aa = pack2(av[r][j]);
                        ffma2(acc[r][0], aa, blo.x);
                        ffma2(acc[r][1], aa, blo.y);
                        ffma2(acc[r][2], aa, bhi.x);
                        ffma2(acc[r][3], aa, bhi.y);
                    }
                }
            }

            // epilogue: relu(acc + qA) . W1, reduce over the 8 tx lanes
            #pragma unroll
            for (int r = 0; r < 4; r++) {
                const int trow = ty * 4 + r;
                float s = 0.f;
                #pragma unroll
                for (int cp = 0; cp < 4; cp++) {
                    float2 v = unpack2(acc[r][cp]);
                    int h = (cp < 2) ? (tx * 4 + cp * 2) : (32 + tx * 4 + (cp - 2) * 2);
                    float x0 = v.x + sqA[h];
                    float x1 = v.y + sqA[h + 1];
                    x0 = x0 > 0.f ? x0 : 0.f;
                    x1 = x1 > 0.f ? x1 : 0.f;
                    s += x0 * w1v[cp * 2] + x1 * w1v[cp * 2 + 1];
                }
                s += __shfl_down_sync(gmask, s, 4);
                s += __shfl_down_sync(gmask, s, 2);
                s += __shfl_down_sync(gmask, s, 1);
                if (tx == 0 && trow < rows)
                    out[b * NT + t0 + trow] = s + b1v;
            }
        }
    }
}

extern "C" void kernel_launch(void* const* d_in, const int* in_sizes, int n_in,
                              void* d_out, int out_size)
{
    const float* query = (const float*)d_in[0];
    const float* keys  = (const float*)d_in[1];
    const float* W0    = (const float*)d_in[2];
    const float* b0    = (const float*)d_in[3];
    const float* W1    = (const float*)d_in[4];
    const float* b1    = (const float*)d_in[5];
    float* out = (float*)d_out;

    const int smem_bytes = (NE * NH + CHUNK * S + NE + NH) * (int)sizeof(float);
    cudaFuncSetAttribute(lau_kernel, cudaFuncAttributeMaxDynamicSharedMemorySize,
                         smem_bytes);
    lau_kernel<<<NB, 256, smem_bytes>>>(query, keys, W0, b0, W1, b1, out);
}

// round 12
// speedup vs baseline: 1.4099x; 1.4099x over previous
#include <cuda_runtime.h>

// LocalActivationUnit: score[b,t] = relu([q,k,q-k,q*k] @ W0 + b0) @ W1 + b1
// Folded:  h = qA_b + k . C_b ; score = relu(h) @ W1 + b1.
//
// R12: back to the balanced 8x8 microtile (128 thr/CTA, 2 CTAs/SM) from R9,
//      plus: A via LDS.128 with XOR-swizzled sA (conflict-free across ty),
//      software-pipelined A (double buffer) and B (1-p prefetch).

#define NB 1024
#define NT 200
#define NE 128
#define NH 64
#define CHUNK 128
#define S 128   // sA row stride in floats (512 B); XOR swizzle handles banks

__device__ __forceinline__ unsigned long long pack2(float x) {
    unsigned long long r;
    asm("mov.b64 %0, {%1, %1};" : "=l"(r) : "r"(__float_as_uint(x)));
    return r;
}
__device__ __forceinline__ void ffma2(unsigned long long &acc, unsigned long long a,
                                      unsigned long long b) {
    asm("fma.rn.f32x2 %0, %1, %2, %0;" : "+l"(acc) : "l"(a), "l"(b));
}
__device__ __forceinline__ float2 unpack2(unsigned long long v) {
    unsigned int lo, hi;
    asm("mov.b64 {%0, %1}, %2;" : "=r"(lo), "=r"(hi) : "l"(v));
    return make_float2(__uint_as_float(lo), __uint_as_float(hi));
}

__global__ void __launch_bounds__(128, 2)
lau_kernel(const float* __restrict__ query,
           const float* __restrict__ keys,
           const float* __restrict__ W0,
           const float* __restrict__ b0,
           const float* __restrict__ W1,
           const float* __restrict__ b1,
           float* __restrict__ out)
{
    extern __shared__ float smem[];
    float* sC  = smem;                 // [128][64] rows in permuted-p order
    float* sA  = smem + NE * NH;       // [CHUNK][S] keys, e-permuted + XOR-swizzled
    float* sq  = sA + CHUNK * S;       // [128]
    float* sqA = sq + NE;              // [64]

    const int tid = threadIdx.x;
    const int b   = blockIdx.x;

    // ---- load q ----
    sq[tid] = query[b * NE + tid];
    __syncthreads();

    // ---- precompute C_b into smem (rows permuted: p -> e(p)=4*(p&31)+(p>>5)) ----
    const float* W0a = W0;
    const float* W0b = W0 + 128 * NH;
    const float* W0c = W0 + 256 * NH;
    const float* W0d = W0 + 384 * NH;
    #pragma unroll
    for (int j = 0; j < 16; j++) {
        int f = tid + 128 * j;          // float4 index, [0, 2048)
        int p = f >> 4;                 // 16 float4 per row
        int c = f & 15;
        int e = 4 * (p & 31) + (p >> 5);
        float qe = sq[e];
        float4 wb = *(const float4*)(W0b + e * NH + c * 4);
        float4 wc = *(const float4*)(W0c + e * NH + c * 4);
        float4 wd = *(const float4*)(W0d + e * NH + c * 4);
        float4 cv;
        cv.x = (wb.x - wc.x) + qe * wd.x;
        cv.y = (wb.y - wc.y) + qe * wd.y;
        cv.z = (wb.z - wc.z) + qe * wd.z;
        cv.w = (wb.w - wc.w) + qe * wd.w;
        *(float4*)&sC[f * 4] = cv;
    }
    // qA partials: 2 groups of 64 e-terms, scratch in sA
    {
        int h = tid & 63, g = tid >> 6;
        float ps = 0.f;
        int e0 = g * 64;
        #pragma unroll 4
        for (int e = e0; e < e0 + 64; e++)
            ps += sq[e] * (W0a[e * NH + h] + W0c[e * NH + h]);
        sA[g * 64 + h] = ps;
    }
    __syncthreads();
    if (tid < NH)
        sqA[tid] = b0[tid] + sA[tid] + sA[64 + tid];
    // (loop-start __syncthreads orders this vs. sA reuse)

    // ---- per-thread constants ----
    const int ty = tid >> 3;            // 0..15 -> 8 rows each
    const int tx = tid & 7;             // 0..7  -> cols {tx*4..+3, 32+tx*4..+3}
    float w1v[8];
    *(float4*)&w1v[0] = *(const float4*)(W1 + tx * 4);
    *(float4*)&w1v[4] = *(const float4*)(W1 + 32 + tx * 4);
    const float b1v = b1[0];
    const float* bp = sC + tx * 4;
    const unsigned gmask = 0xffu << ((tid & 31) & 24);  // 8-lane shfl group
    const int swz = (ty & 3) << 3;      // A-read XOR swizzle (bits 3..4 of slot)

    // ---- main loop over T in 128-row chunks ----
    for (int t0 = 0; t0 < NT; t0 += CHUNK) {
        const int rows = min(CHUNK, NT - t0);
        __syncthreads();   // previous GEMM done reading sA

        // loader: lane c4 of each row scatters its 4 floats to word groups
        // 32*(m ^ ((row>>3)&3)) + c4 (XOR permutes 128-B lines within the row;
        // per-instruction banks = c4 + const -> conflict-free)
        for (int f = tid; f < rows * 32; f += 128) {
            int row = f >> 5, c4 = f & 31;
            float4 v = *(const float4*)(keys + ((long)b * NT + t0 + row) * NE + c4 * 4);
            int sw = (row >> 3) & 3;
            float* base = sA + row * S + c4;
            base[32 * (0 ^ sw)] = v.x;
            base[32 * (1 ^ sw)] = v.y;
            base[32 * (2 ^ sw)] = v.z;
            base[32 * (3 ^ sw)] = v.w;
        }
        __syncthreads();

        if (ty * 8 < rows) {
            // GEMM: acc[8 rows][4 col-pairs], K=128 (permuted order, matches sC)
            unsigned long long acc[8][4];
            #pragma unroll
            for (int r = 0; r < 8; r++)
                #pragma unroll
                for (int c = 0; c < 4; c++) acc[r][c] = 0ull;

            const float4* arow[8];
            #pragma unroll
            for (int r = 0; r < 8; r++)
                arow[r] = (const float4*)(sA + (ty * 8 + r) * S);

            // software pipeline: av double buffer (A), 1-ahead B prefetch
            float4 av[2][8];
            #pragma unroll
            for (int r = 0; r < 8; r++) av[0][r] = arow[r][0 ^ swz];
            ulonglong2 cb_lo = *(const ulonglong2*)(bp);
            ulonglong2 cb_hi = *(const ulonglong2*)(bp + 32);

            #pragma unroll 2
            for (int pb = 0; pb < 32; pb++) {
                const int buf = pb & 1;
                // prefetch next A block into the other buffer
                if (pb < 31) {
                    #pragma unroll
                    for (int r = 0; r < 8; r++)
                        av[buf ^ 1][r] = arow[r][(pb + 1) ^ swz];
                }
                #pragma unroll
                for (int j = 0; j < 4; j++) {
                    const int p = pb * 4 + j;
                    // prefetch next B
                    const int pn = (p < 127) ? p + 1 : 127;
                    ulonglong2 nb_lo = *(const ulonglong2*)(bp + pn * NH);
                    ulonglong2 nb_hi = *(const ulonglong2*)(bp + pn * NH + 32);
                    const float* avf = (const float*)&av[buf][0];
                    #pragma unroll
                    for (int r = 0; r < 8; r++) {
                        unsigned long long aa = pack2(avf[r * 4 + j]);
                        ffma2(acc[r][0], aa, cb_lo.x);
                        ffma2(acc[r][1], aa, cb_lo.y);
                        ffma2(acc[r][2], aa, cb_hi.x);
                        ffma2(acc[r][3], aa, cb_hi.y);
                    }
                    cb_lo = nb_lo;
                    cb_hi = nb_hi;
                }
            }

            // epilogue: relu(acc + qA) . W1, reduce over the 8 tx lanes
            #pragma unroll
            for (int r = 0; r < 8; r++) {
                const int trow = ty * 8 + r;
                float s = 0.f;
                #pragma unroll
                for (int cp = 0; cp < 4; cp++) {
                    float2 v = unpack2(acc[r][cp]);
                    int h = (cp < 2) ? (tx * 4 + cp * 2) : (32 + tx * 4 + (cp - 2) * 2);
                    float x0 = v.x + sqA[h];
                    float x1 = v.y + sqA[h + 1];
                    x0 = x0 > 0.f ? x0 : 0.f;
                    x1 = x1 > 0.f ? x1 : 0.f;
                    s += x0 * w1v[cp * 2] + x1 * w1v[cp * 2 + 1];
                }
                s += __shfl_down_sync(gmask, s, 4);
                s += __shfl_down_sync(gmask, s, 2);
                s += __shfl_down_sync(gmask, s, 1);
                if (tx == 0 && trow < rows)
                    out[b * NT + t0 + trow] = s + b1v;
            }
        }
    }
}

extern "C" void kernel_launch(void* const* d_in, const int* in_sizes, int n_in,
                              void* d_out, int out_size)
{
    const float* query = (const float*)d_in[0];
    const float* keys  = (const float*)d_in[1];
    const float* W0    = (const float*)d_in[2];
    const float* b0    = (const float*)d_in[3];
    const float* W1    = (const float*)d_in[4];
    const float* b1    = (const float*)d_in[5];
    float* out = (float*)d_out;

    const int smem_bytes = (NE * NH + CHUNK * S + NE + NH) * (int)sizeof(float);
    cudaFuncSetAttribute(lau_kernel, cudaFuncAttributeMaxDynamicSharedMemorySize,
                         smem_bytes);
    lau_kernel<<<NB, 128, smem_bytes>>>(query, keys, W0, b0, W1, b1, out);
}